// round 1
// baseline (speedup 1.0000x reference)
#include <cuda_runtime.h>
#include <cuda_bf16.h>

#define Bsz 4
#define SEQ 2048
#define CH  512
#define NH  8
#define DKd 64
#define DVd 64
#define KSZ 3

// Scratch for projected q, k, v in [B, H, S, D] layout (16 MB each).
__device__ float g_q[Bsz * NH * SEQ * DKd];
__device__ float g_k[Bsz * NH * SEQ * DKd];
__device__ float g_v[Bsz * NH * SEQ * DVd];

// ---------------------------------------------------------------------------
// Kernel 1: fused QKV projection.
// q,k are causal conv1d (kernel 3, left pad 2) == GEMM with implicit im2col,
// K = 3*512 = 1536. v is a plain GEMM, K = 512.
// Output matrix is [B*S, 1536] split as [q(512) | k(512) | v(512)].
// Tile: 64 positions x 64 out-channels, 256 threads, 4x4 micro-tile, Kc=16.
// ---------------------------------------------------------------------------
__global__ void qkv_kernel(const float* __restrict__ x,
                           const float* __restrict__ wq, const float* __restrict__ bq,
                           const float* __restrict__ wk, const float* __restrict__ bk,
                           const float* __restrict__ wv, const float* __restrict__ bv)
{
    const int mt = blockIdx.x;            // 0..127  (B*S / 64)
    const int nt = blockIdx.y;            // 0..23
    const int seg = nt >> 3;              // 0 = q, 1 = k, 2 = v
    const int oc0 = (nt & 7) * 64;

    const int s_glob0 = mt * 64;          // tile never crosses a batch (2048 % 64 == 0)
    const int b   = s_glob0 / SEQ;
    const int sl0 = s_glob0 % SEQ;

    const float* w    = (seg == 0) ? wq : (seg == 1) ? wk : wv;
    const float* bias = (seg == 0) ? bq : (seg == 1) ? bk : bv;
    const int KK = (seg < 2) ? (CH * KSZ) : CH;

    __shared__ float As[16][65];
    __shared__ float Bs[16][65];

    const int tid = threadIdx.x;
    const int tx = tid & 15, ty = tid >> 4;

    float acc[4][4];
#pragma unroll
    for (int i = 0; i < 4; i++)
#pragma unroll
        for (int j = 0; j < 4; j++) acc[i][j] = 0.f;

    for (int k0 = 0; k0 < KK; k0 += 16) {
        // --- load X tile (im2col for conv segments) ---
        for (int l = tid; l < 16 * 64; l += 256) {
            const int kk = l >> 6, m = l & 63;
            const int kg = k0 + kk;
            float v;
            if (seg < 2) {
                const int t = kg >> 9;          // tap (kg / 512); chunk of 16 never crosses taps
                const int c = kg & 511;
                const int srow = sl0 + m + t - 2;
                v = (srow >= 0) ? x[(b * SEQ + srow) * CH + c] : 0.f;
            } else {
                v = x[(b * SEQ + sl0 + m) * CH + kg];
            }
            As[kk][m] = v;
        }
        // --- load W tile (consecutive threads take consecutive kk -> near-contig gmem) ---
        for (int l = tid; l < 16 * 64; l += 256) {
            const int n = l >> 4, kk = l & 15;
            const int kg = k0 + kk;
            float v;
            if (seg < 2) {
                const int t = kg >> 9, c = kg & 511;
                v = w[(oc0 + n) * (CH * KSZ) + c * KSZ + t];
            } else {
                v = w[(oc0 + n) * CH + kg];
            }
            Bs[kk][n] = v;
        }
        __syncthreads();

#pragma unroll
        for (int kk = 0; kk < 16; kk++) {
            float a[4], bb[4];
#pragma unroll
            for (int i = 0; i < 4; i++) a[i] = As[kk][ty * 4 + i];
#pragma unroll
            for (int j = 0; j < 4; j++) bb[j] = Bs[kk][tx * 4 + j];
#pragma unroll
            for (int i = 0; i < 4; i++)
#pragma unroll
                for (int j = 0; j < 4; j++) acc[i][j] += a[i] * bb[j];
        }
        __syncthreads();
    }

    float* dst = (seg == 0) ? g_q : (seg == 1) ? g_k : g_v;
#pragma unroll
    for (int i = 0; i < 4; i++) {
        const int s = sl0 + ty * 4 + i;
#pragma unroll
        for (int j = 0; j < 4; j++) {
            const int oc = oc0 + tx * 4 + j;
            const int h = oc >> 6, d = oc & 63;
            dst[((b * NH + h) * SEQ + s) * DKd + d] = acc[i][j] + bias[oc];
        }
    }
}

// ---------------------------------------------------------------------------
// Kernel 2: attention. One block per (b, h, 8-row tile). 256 threads.
// Full energy rows (<= 2048 entries) kept in dynamic smem -> exact softmax,
// attention written with exact zeros above the diagonal (matches reference:
// exp(-1e10 - m) underflows to 0 in fp32).
// ---------------------------------------------------------------------------
__global__ void attn_kernel(float* __restrict__ out, float* __restrict__ attn)
{
    extern __shared__ float sm[];
    float* q_s = sm;                  // 8*64   = 512 floats
    float* e   = sm + 512;            // 8*2048 = 16384 floats
    float* red = sm + 512 + 16384;    // 4*8*64 = 2048 floats

    const int bh = blockIdx.y;              // 0..31
    const int b = bh >> 3, h = bh & 7;
    const int r0 = blockIdx.x * 8;
    const int tid = threadIdx.x;

    const float* qp = g_q + (bh * SEQ + r0) * DKd;
    const float* kp = g_k + bh * SEQ * DKd;
    const float* vp = g_v + bh * SEQ * DVd;

    for (int l = tid; l < 8 * 64; l += 256) q_s[l] = qp[l];
    __syncthreads();

    const int imax = r0 + 7;
    const float sc = 0.125f;   // 1/sqrt(64)

    // --- scores: each thread owns key j, computes dot vs all 8 q rows ---
    for (int j = tid; j <= imax; j += 256) {
        const float4* k4 = (const float4*)(kp + j * DKd);
        float a[8];
#pragma unroll
        for (int r = 0; r < 8; r++) a[r] = 0.f;
#pragma unroll
        for (int c = 0; c < 16; c++) {
            const float4 kv = k4[c];
#pragma unroll
            for (int r = 0; r < 8; r++) {
                const float4 qv = ((const float4*)(q_s + r * 64))[c];
                a[r] += kv.x * qv.x + kv.y * qv.y + kv.z * qv.z + kv.w * qv.w;
            }
        }
#pragma unroll
        for (int r = 0; r < 8; r++) e[r * SEQ + j] = a[r] * sc;
    }
    __syncthreads();

    // --- softmax: warp r handles row r0+r ---
    {
        const int warp = tid >> 5, lane = tid & 31;
        const int r = warp;
        const int ir = r0 + r;
        float m = -1e30f;
        for (int j = lane; j <= ir; j += 32) m = fmaxf(m, e[r * SEQ + j]);
#pragma unroll
        for (int o = 16; o; o >>= 1) m = fmaxf(m, __shfl_xor_sync(~0u, m, o));
        float l = 0.f;
        for (int j = lane; j <= ir; j += 32) {
            const float t = expf(e[r * SEQ + j] - m);
            e[r * SEQ + j] = t;
            l += t;
        }
#pragma unroll
        for (int o = 16; o; o >>= 1) l += __shfl_xor_sync(~0u, l, o);
        const float inv = 1.f / l;
        float* arow = attn + ((size_t)(bh * SEQ + ir)) * SEQ;
        for (int j = lane; j < SEQ; j += 32) {
            if (j <= ir) {
                const float p = e[r * SEQ + j] * inv;
                e[r * SEQ + j] = p;
                arow[j] = p;
            } else {
                arow[j] = 0.f;
            }
        }
    }
    __syncthreads();

    // --- out = P @ V : thread (part = tid>>6, d = tid&63), v load shared by 8 rows ---
    const int part = tid >> 6, d = tid & 63;
    float acc[8];
#pragma unroll
    for (int r = 0; r < 8; r++) acc[r] = 0.f;
    for (int j = part; j <= imax; j += 4) {
        const float vjd = vp[j * DVd + d];
#pragma unroll
        for (int r = 0; r < 8; r++) {
            if (j <= r0 + r) acc[r] += e[r * SEQ + j] * vjd;
        }
    }
    __syncthreads();
#pragma unroll
    for (int r = 0; r < 8; r++) red[(part * 8 + r) * 64 + d] = acc[r];
    __syncthreads();
    if (part == 0) {
#pragma unroll
        for (int r = 0; r < 8; r++) {
            const float s = red[(0 * 8 + r) * 64 + d] + red[(1 * 8 + r) * 64 + d]
                          + red[(2 * 8 + r) * 64 + d] + red[(3 * 8 + r) * 64 + d];
            out[((b * SEQ + (r0 + r)) * NH + h) * DVd + d] = s;
        }
    }
}

extern "C" void kernel_launch(void* const* d_in, const int* in_sizes, int n_in,
                              void* d_out, int out_size)
{
    const float* x  = (const float*)d_in[0];
    // d_in[1] = mask (causal, known statically) — unused
    const float* wq = (const float*)d_in[2];
    const float* bq = (const float*)d_in[3];
    const float* wk = (const float*)d_in[4];
    const float* bk = (const float*)d_in[5];
    const float* wv = (const float*)d_in[6];
    const float* bv = (const float*)d_in[7];

    float* out  = (float*)d_out;
    float* attn = out + (size_t)Bsz * SEQ * NH * DVd;   // out first, then attention

    qkv_kernel<<<dim3(128, 24), 256>>>(x, wq, bq, wk, bk, wv, bv);

    const int smem_bytes = (512 + 8 * SEQ + 2048) * sizeof(float);  // 75776
    cudaFuncSetAttribute(attn_kernel, cudaFuncAttributeMaxDynamicSharedMemorySize, smem_bytes);
    attn_kernel<<<dim3(SEQ / 8, Bsz * NH), 256, smem_bytes>>>(out, attn);
}

// round 2
// speedup vs baseline: 3.2508x; 3.2508x over previous
#include <cuda_runtime.h>
#include <cuda_bf16.h>

#define Bsz 4
#define SEQ 2048
#define CH  512
#define NH  8
#define DKd 64
#define DVd 64

// Scratch: projected q,k,v in [B,H,S,D] layout, and repacked weights.
__device__ float g_q[Bsz * NH * SEQ * DKd];
__device__ float g_k[Bsz * NH * SEQ * DKd];
__device__ float g_v[Bsz * NH * SEQ * DVd];
__device__ float g_wqt[1536 * 512];   // [kg = t*512+c][oc]
__device__ float g_wkt[1536 * 512];
__device__ float g_wvt[512 * 512];    // [c][oc]

// ---------------------------------------------------------------------------
// Repack weights: conv weights wq/wk [oc][c][tap] -> [t*512+c][oc];
// wv [oc][c] -> [c][oc]. Makes GEMM B-tile loads fully coalesced.
// ---------------------------------------------------------------------------
__global__ void repack_kernel(const float* __restrict__ wq,
                              const float* __restrict__ wk,
                              const float* __restrict__ wv)
{
    const int i = blockIdx.x * blockDim.x + threadIdx.x;
    if (i >= 1536 * 512) return;
    const int kg = i >> 9, oc = i & 511;
    const int t = kg / 512, c = kg % 512;
    g_wqt[i] = wq[oc * 1536 + c * 3 + t];
    g_wkt[i] = wk[oc * 1536 + c * 3 + t];
    if (kg < 512) g_wvt[i] = wv[oc * 512 + kg];
}

// ---------------------------------------------------------------------------
// QKV projection GEMM. M = B*S = 8192 rows (im2col over x for q/k, K=1536;
// plain GEMM for v, K=512). Tile 128x128, Kc=8, 256 threads, 8x8 micro-tile.
// ---------------------------------------------------------------------------
__global__ void __launch_bounds__(256)
qkv_gemm(const float* __restrict__ x,
         const float* __restrict__ bq, const float* __restrict__ bk,
         const float* __restrict__ bv)
{
    const int mt = blockIdx.x;           // 64 tiles of 128 rows
    const int nt = blockIdx.y;           // 12
    const int seg = nt >> 2;             // 0=q,1=k,2=v
    const int oc0 = (nt & 3) * 128;
    const int gm0 = mt * 128;            // never crosses a batch
    const int b   = gm0 >> 11;
    const int sl0 = gm0 & 2047;
    const int KK = (seg < 2) ? 1536 : 512;
    const float* Wt   = (seg == 0) ? g_wqt : (seg == 1) ? g_wkt : g_wvt;
    const float* bias = (seg == 0) ? bq   : (seg == 1) ? bk   : bv;
    float* dst        = (seg == 0) ? g_q  : (seg == 1) ? g_k  : g_v;

    __shared__ float As[8][128];
    __shared__ float Bs[8][128];

    const int tid = threadIdx.x;
    const int tx = tid & 15, ty = tid >> 4;

    float acc[8][8];
#pragma unroll
    for (int i = 0; i < 8; i++)
#pragma unroll
        for (int j = 0; j < 8; j++) acc[i][j] = 0.f;

    const int am = tid >> 1;             // 0..127 (row within tile)
    const int aq = tid & 1;              // kg quad
    const int bkk = tid >> 5;            // 0..7
    const int bn  = (tid & 31) * 4;      // 0..124

    for (int k0 = 0; k0 < KK; k0 += 8) {
        // --- A tile (im2col) ---
        {
            const int kg = k0 + aq * 4;
            int srow, c;
            if (seg < 2) { const int t = kg >> 9; c = kg & 511; srow = sl0 + am + t - 2; }
            else         { c = kg; srow = sl0 + am; }
            float4 v = make_float4(0.f, 0.f, 0.f, 0.f);
            if (srow >= 0)
                v = *(const float4*)(x + (((size_t)(b * SEQ + srow)) << 9) + c);
            As[aq * 4 + 0][am] = v.x;
            As[aq * 4 + 1][am] = v.y;
            As[aq * 4 + 2][am] = v.z;
            As[aq * 4 + 3][am] = v.w;
        }
        // --- B tile (repacked weights: coalesced) ---
        *(float4*)&Bs[bkk][bn] =
            *(const float4*)(Wt + (size_t)(k0 + bkk) * 512 + oc0 + bn);
        __syncthreads();

#pragma unroll
        for (int c = 0; c < 8; c++) {
            const float4 a0 = *(const float4*)&As[c][ty * 4];
            const float4 a1 = *(const float4*)&As[c][64 + ty * 4];
            const float4 b0 = *(const float4*)&Bs[c][tx * 4];
            const float4 b1 = *(const float4*)&Bs[c][64 + tx * 4];
            const float a[8]  = {a0.x, a0.y, a0.z, a0.w, a1.x, a1.y, a1.z, a1.w};
            const float bb[8] = {b0.x, b0.y, b0.z, b0.w, b1.x, b1.y, b1.z, b1.w};
#pragma unroll
            for (int i = 0; i < 8; i++)
#pragma unroll
                for (int j = 0; j < 8; j++) acc[i][j] += a[i] * bb[j];
        }
        __syncthreads();
    }

    // --- store with bias, scatter to [B,H,S,D] ---
#pragma unroll
    for (int g = 0; g < 2; g++) {
#pragma unroll
        for (int i = 0; i < 4; i++) {
            const int s = sl0 + g * 64 + ty * 4 + i;
#pragma unroll
            for (int gg = 0; gg < 2; gg++) {
                const int oc = oc0 + gg * 64 + tx * 4;
                const int h = oc >> 6, d = oc & 63;
                float4 o;
                o.x = acc[g * 4 + i][gg * 4 + 0] + bias[oc + 0];
                o.y = acc[g * 4 + i][gg * 4 + 1] + bias[oc + 1];
                o.z = acc[g * 4 + i][gg * 4 + 2] + bias[oc + 2];
                o.w = acc[g * 4 + i][gg * 4 + 3] + bias[oc + 3];
                *(float4*)(dst + (((size_t)((b * NH + h) * SEQ + s)) << 6) + d) = o;
            }
        }
    }
}

// ---------------------------------------------------------------------------
// Scores: e[bh][r][j] = (q . k) / 8 for 128x128 tiles with jt <= rt.
// Written into the attention output buffer (used as scratch until softmax).
// ---------------------------------------------------------------------------
__global__ void __launch_bounds__(256)
scores_kernel(float* __restrict__ attn)
{
    const int jt = blockIdx.x, rt = blockIdx.y, bh = blockIdx.z;
    if (jt > rt) return;
    extern __shared__ float sm[];
    float* Qs = sm;                 // [64][132]  (c-major, transposed)
    float* Ks = sm + 64 * 132;      // [64][128]

    const int r0 = rt * 128, j0 = jt * 128;
    const int tid = threadIdx.x;

#pragma unroll
    for (int it = 0; it < 8; it++) {
        const int id = tid + it * 256;          // 2048
        const int r = id >> 4, c4 = (id & 15) * 4;
        const float4 v = *(const float4*)(g_q + (((size_t)bh * SEQ) + r0 + r) * 64 + c4);
        Qs[(c4 + 0) * 132 + r] = v.x;
        Qs[(c4 + 1) * 132 + r] = v.y;
        Qs[(c4 + 2) * 132 + r] = v.z;
        Qs[(c4 + 3) * 132 + r] = v.w;
    }
#pragma unroll
    for (int it = 0; it < 8; it++) {
        const int id = tid + it * 256;
        const int j = id >> 4, c4 = (id & 15) * 4;
        const float4 v = *(const float4*)(g_k + (((size_t)bh * SEQ) + j0 + j) * 64 + c4);
        Ks[(c4 + 0) * 128 + j] = v.x;
        Ks[(c4 + 1) * 128 + j] = v.y;
        Ks[(c4 + 2) * 128 + j] = v.z;
        Ks[(c4 + 3) * 128 + j] = v.w;
    }
    __syncthreads();

    const int tx = tid & 15, ty = tid >> 4;
    float acc[8][8];
#pragma unroll
    for (int i = 0; i < 8; i++)
#pragma unroll
        for (int j = 0; j < 8; j++) acc[i][j] = 0.f;

#pragma unroll 16
    for (int c = 0; c < 64; c++) {
        const float4 a0 = *(const float4*)&Qs[c * 132 + ty * 4];
        const float4 a1 = *(const float4*)&Qs[c * 132 + 64 + ty * 4];
        const float4 b0 = *(const float4*)&Ks[c * 128 + tx * 4];
        const float4 b1 = *(const float4*)&Ks[c * 128 + 64 + tx * 4];
        const float a[8]  = {a0.x, a0.y, a0.z, a0.w, a1.x, a1.y, a1.z, a1.w};
        const float bb[8] = {b0.x, b0.y, b0.z, b0.w, b1.x, b1.y, b1.z, b1.w};
#pragma unroll
        for (int i = 0; i < 8; i++)
#pragma unroll
            for (int j = 0; j < 8; j++) acc[i][j] += a[i] * bb[j];
    }

#pragma unroll
    for (int g = 0; g < 2; g++) {
#pragma unroll
        for (int i = 0; i < 4; i++) {
            const int r = r0 + g * 64 + ty * 4 + i;
            float* ep = attn + (((size_t)bh * SEQ) + r) * SEQ + j0;
#pragma unroll
            for (int gg = 0; gg < 2; gg++) {
                float4 o;
                o.x = acc[g * 4 + i][gg * 4 + 0] * 0.125f;
                o.y = acc[g * 4 + i][gg * 4 + 1] * 0.125f;
                o.z = acc[g * 4 + i][gg * 4 + 2] * 0.125f;
                o.w = acc[g * 4 + i][gg * 4 + 3] * 0.125f;
                *(float4*)(ep + gg * 64 + tx * 4) = o;
            }
        }
    }
}

// ---------------------------------------------------------------------------
// Softmax: one block per row. Row kept in <=8 registers/thread; writes exact
// zeros above the diagonal (matches reference exp(-1e10-m) fp32 underflow).
// ---------------------------------------------------------------------------
__global__ void __launch_bounds__(256)
softmax_kernel(float* __restrict__ attn)
{
    const int row = blockIdx.x;               // 65536
    const int bh = row >> 11, sl = row & 2047;
    float* e = attn + (((size_t)bh * SEQ) + sl) * SEQ;
    const int len = sl + 1;
    const int tid = threadIdx.x;

    float buf[8];
    int cnt = 0;
    float m = -1e30f;
    for (int j = tid; j < len; j += 256) {
        const float v = e[j];
        buf[cnt++] = v;
        m = fmaxf(m, v);
    }
    __shared__ float red[8];
#pragma unroll
    for (int o = 16; o; o >>= 1) m = fmaxf(m, __shfl_xor_sync(~0u, m, o));
    if ((tid & 31) == 0) red[tid >> 5] = m;
    __syncthreads();
    const float M = fmaxf(fmaxf(fmaxf(red[0], red[1]), fmaxf(red[2], red[3])),
                          fmaxf(fmaxf(red[4], red[5]), fmaxf(red[6], red[7])));
    __syncthreads();

    float s = 0.f;
    for (int i = 0; i < cnt; i++) { buf[i] = __expf(buf[i] - M); s += buf[i]; }
#pragma unroll
    for (int o = 16; o; o >>= 1) s += __shfl_xor_sync(~0u, s, o);
    if ((tid & 31) == 0) red[tid >> 5] = s;
    __syncthreads();
    const float inv = 1.f / (red[0] + red[1] + red[2] + red[3] +
                             red[4] + red[5] + red[6] + red[7]);

    cnt = 0;
    for (int j = tid; j < SEQ; j += 256) {
        float v = 0.f;
        if (j < len) v = buf[cnt++] * inv;
        e[j] = v;
    }
}

// ---------------------------------------------------------------------------
// PV: out[r][d] = sum_j P[r][j] * v[j][d]. Tile 128r x 64d per block; P is
// already exactly zero above the diagonal, so no masking needed.
// ---------------------------------------------------------------------------
__global__ void __launch_bounds__(256)
pv_kernel(const float* __restrict__ attn, float* __restrict__ out)
{
    const int rt = blockIdx.x;            // 16
    const int bh = blockIdx.y;            // 32
    const int b = bh >> 3, h = bh & 7;
    const int r0 = rt * 128;
    extern __shared__ float sm[];
    float* Ps = sm;                        // [64][132] (j-major, transposed)
    float* Vs = sm + 64 * 132;             // [64][64]

    const int tid = threadIdx.x;
    const int tx = tid & 15, ty = tid >> 4;

    float acc[8][4];
#pragma unroll
    for (int i = 0; i < 8; i++)
#pragma unroll
        for (int l = 0; l < 4; l++) acc[i][l] = 0.f;

    const int jmax = r0 + 128;
    for (int j0 = 0; j0 < jmax; j0 += 64) {
#pragma unroll
        for (int it = 0; it < 8; it++) {
            const int id = tid + it * 256;       // 2048
            const int r = id >> 4, jj4 = (id & 15) * 4;
            const float4 v = *(const float4*)(attn + (((size_t)bh * SEQ) + r0 + r) * SEQ + j0 + jj4);
            Ps[(jj4 + 0) * 132 + r] = v.x;
            Ps[(jj4 + 1) * 132 + r] = v.y;
            Ps[(jj4 + 2) * 132 + r] = v.z;
            Ps[(jj4 + 3) * 132 + r] = v.w;
        }
#pragma unroll
        for (int it = 0; it < 4; it++) {
            const int id = tid + it * 256;       // 1024
            const int jj = id >> 4, d4 = (id & 15) * 4;
            *(float4*)&Vs[jj * 64 + d4] =
                *(const float4*)(g_v + (((size_t)bh * SEQ) + j0 + jj) * 64 + d4);
        }
        __syncthreads();

#pragma unroll 16
        for (int jj = 0; jj < 64; jj++) {
            const float4 a0 = *(const float4*)&Ps[jj * 132 + ty * 4];
            const float4 a1 = *(const float4*)&Ps[jj * 132 + 64 + ty * 4];
            const float4 b0 = *(const float4*)&Vs[jj * 64 + tx * 4];
            const float a[8]  = {a0.x, a0.y, a0.z, a0.w, a1.x, a1.y, a1.z, a1.w};
            const float bb[4] = {b0.x, b0.y, b0.z, b0.w};
#pragma unroll
            for (int i = 0; i < 8; i++)
#pragma unroll
                for (int l = 0; l < 4; l++) acc[i][l] += a[i] * bb[l];
        }
        __syncthreads();
    }

#pragma unroll
    for (int g = 0; g < 2; g++) {
#pragma unroll
        for (int i = 0; i < 4; i++) {
            const int s = r0 + g * 64 + ty * 4 + i;
            float4 o;
            o.x = acc[g * 4 + i][0];
            o.y = acc[g * 4 + i][1];
            o.z = acc[g * 4 + i][2];
            o.w = acc[g * 4 + i][3];
            *(float4*)(out + ((((size_t)(b * SEQ + s)) * NH + h) << 6) + tx * 4) = o;
        }
    }
}

extern "C" void kernel_launch(void* const* d_in, const int* in_sizes, int n_in,
                              void* d_out, int out_size)
{
    const float* x  = (const float*)d_in[0];
    // d_in[1] = mask (static causal) — unused
    const float* wq = (const float*)d_in[2];
    const float* bq = (const float*)d_in[3];
    const float* wk = (const float*)d_in[4];
    const float* bk = (const float*)d_in[5];
    const float* wv = (const float*)d_in[6];
    const float* bv = (const float*)d_in[7];

    float* out  = (float*)d_out;
    float* attn = out + (size_t)Bsz * SEQ * NH * DVd;

    repack_kernel<<<(1536 * 512 + 255) / 256, 256>>>(wq, wk, wv);
    qkv_gemm<<<dim3(64, 12), 256>>>(x, bq, bk, bv);

    const int sc_smem = (64 * 132 + 64 * 128) * sizeof(float);   // 66560
    cudaFuncSetAttribute(scores_kernel, cudaFuncAttributeMaxDynamicSharedMemorySize, sc_smem);
    scores_kernel<<<dim3(16, 16, 32), 256, sc_smem>>>(attn);

    softmax_kernel<<<Bsz * NH * SEQ, 256>>>(attn);

    const int pv_smem = (64 * 132 + 64 * 64) * sizeof(float);    // 50176
    cudaFuncSetAttribute(pv_kernel, cudaFuncAttributeMaxDynamicSharedMemorySize, pv_smem);
    pv_kernel<<<dim3(16, 32), 256, pv_smem>>>(attn, out);
}

// round 3
// speedup vs baseline: 6.9903x; 2.1503x over previous
#include <cuda_runtime.h>
#include <cuda_bf16.h>
#include <cstdint>

#define Bsz 4
#define SEQ 2048
#define CH  512
#define NH  8

typedef __nv_bfloat16 bf16;

// split-bf16 operand storage
__device__ bf16 g_xh[Bsz*SEQ*CH], g_xl[Bsz*SEQ*CH];
__device__ bf16 g_wqh[CH*3*CH], g_wql[CH*3*CH];        // [oc][kg=t*512+c]
__device__ bf16 g_wkh[CH*3*CH], g_wkl[CH*3*CH];
__device__ bf16 g_wvh[CH*CH],   g_wvl[CH*CH];          // [oc][c]
__device__ bf16 g_qh[Bsz*NH*SEQ*64], g_ql[Bsz*NH*SEQ*64];   // [b,h,s,d]
__device__ bf16 g_kh[Bsz*NH*SEQ*64], g_kl[Bsz*NH*SEQ*64];   // [b,h,s,d]
__device__ bf16 g_vth[Bsz*NH*64*SEQ], g_vtl[Bsz*NH*64*SEQ]; // [b,h,d,s] (transposed)

__device__ __forceinline__ void split2(float x, bf16& h, bf16& l) {
    h = __float2bfloat16(x);
    l = __float2bfloat16(x - __bfloat162float(h));
}

// ---- mma helpers (canonical m16n8k16, A row-major via x4 ldmatrix; B staged
// n-major [n][k] and loaded with non-trans x2: lane l<16 -> &B[n0+(l&7)][kk+((l>>3)&1)*8]) ----
__device__ __forceinline__ void ldmA4(uint32_t* a, const bf16* p) {
    uint32_t addr = (uint32_t)__cvta_generic_to_shared(p);
    asm volatile("ldmatrix.sync.aligned.m8n8.x4.shared.b16 {%0,%1,%2,%3}, [%4];"
        : "=r"(a[0]), "=r"(a[1]), "=r"(a[2]), "=r"(a[3]) : "r"(addr));
}
__device__ __forceinline__ void ldmB2(uint32_t* b, const bf16* p) {
    uint32_t addr = (uint32_t)__cvta_generic_to_shared(p);
    asm volatile("ldmatrix.sync.aligned.m8n8.x2.shared.b16 {%0,%1}, [%2];"
        : "=r"(b[0]), "=r"(b[1]) : "r"(addr));
}
__device__ __forceinline__ void mma_bf16(float* d, const uint32_t* a, const uint32_t* b) {
    asm volatile("mma.sync.aligned.m16n8k16.row.col.f32.bf16.bf16.f32 "
        "{%0,%1,%2,%3}, {%4,%5,%6,%7}, {%8,%9}, {%0,%1,%2,%3};"
        : "+f"(d[0]), "+f"(d[1]), "+f"(d[2]), "+f"(d[3])
        : "r"(a[0]), "r"(a[1]), "r"(a[2]), "r"(a[3]), "r"(b[0]), "r"(b[1]));
}

// ---------------------------------------------------------------------------
__global__ void split_x_kernel(const float* __restrict__ x)
{
    const int i = blockIdx.x * 256 + threadIdx.x;
    if (i >= Bsz*SEQ*CH) return;
    split2(x[i], g_xh[i], g_xl[i]);
}

__global__ void repack_kernel(const float* __restrict__ wq,
                              const float* __restrict__ wk,
                              const float* __restrict__ wv)
{
    const int i = blockIdx.x * 256 + threadIdx.x;
    if (i >= CH * 1536) return;
    const int oc = i / 1536, kg = i % 1536;
    const int c = kg & 511, t = kg >> 9;
    split2(wq[oc*1536 + c*3 + t], g_wqh[i], g_wql[i]);
    split2(wk[oc*1536 + c*3 + t], g_wkh[i], g_wkl[i]);
    if (kg < CH) split2(wv[oc*CH + kg], g_wvh[oc*CH + kg], g_wvl[oc*CH + kg]);
}

// ---------------------------------------------------------------------------
// QKV GEMM on tensor cores. Block tile 128(M=positions) x 128(N=out-chan),
// Kc=32. 8 warps (4x2), warp tile 32x64. bf16x3 split accumulation in fp32.
// ---------------------------------------------------------------------------
__global__ void __launch_bounds__(256)
qkv_gemm(const float* __restrict__ bq, const float* __restrict__ bk,
         const float* __restrict__ bv)
{
    const int mt = blockIdx.x;            // 64
    const int nt = blockIdx.y;            // 12
    const int seg = nt >> 2;              // 0=q,1=k,2=v
    const int oc0 = (nt & 3) * 128;
    const int gm0 = mt * 128;
    const int b = gm0 >> 11, sl0 = gm0 & 2047;
    const int KK = (seg < 2) ? 1536 : 512;
    const bf16* Wh = (seg == 0) ? g_wqh : (seg == 1) ? g_wkh : g_wvh;
    const bf16* Wl = (seg == 0) ? g_wql : (seg == 1) ? g_wkl : g_wvl;
    const float* bias = (seg == 0) ? bq : (seg == 1) ? bk : bv;

    __shared__ bf16 Ah[128][40], Al[128][40];   // [m][k]
    __shared__ bf16 Bh[128][40], Bl[128][40];   // [n][k]

    const int tid = threadIdx.x, lane = tid & 31, wid = tid >> 5;
    const int m0 = (wid >> 1) * 32, n0 = (wid & 1) * 64;

    float acc[2][8][4];
#pragma unroll
    for (int i = 0; i < 2; i++)
#pragma unroll
        for (int j = 0; j < 8; j++)
#pragma unroll
            for (int c = 0; c < 4; c++) acc[i][j][c] = 0.f;

    for (int k0 = 0; k0 < KK; k0 += 32) {
#pragma unroll
        for (int it = 0; it < 2; it++) {
            const int idx = tid + it * 256;
            const int row = idx >> 2, q8 = (idx & 3) * 8;
            int srow, c;
            if (seg < 2) { c = (k0 & 511) + q8; srow = sl0 + row + (k0 >> 9) - 2; }
            else         { c = k0 + q8;         srow = sl0 + row; }
            uint4 vh = make_uint4(0,0,0,0), vl = make_uint4(0,0,0,0);
            if (srow >= 0) {
                const size_t off = (((size_t)(b * SEQ + srow)) << 9) + c;
                vh = *(const uint4*)(g_xh + off);
                vl = *(const uint4*)(g_xl + off);
            }
            *(uint4*)&Ah[row][q8] = vh;
            *(uint4*)&Al[row][q8] = vl;
        }
#pragma unroll
        for (int it = 0; it < 2; it++) {
            const int idx = tid + it * 256;
            const int n = idx >> 2, q8 = (idx & 3) * 8;
            const size_t off = (size_t)(oc0 + n) * KK + k0 + q8;
            *(uint4*)&Bh[n][q8] = *(const uint4*)(Wh + off);
            *(uint4*)&Bl[n][q8] = *(const uint4*)(Wl + off);
        }
        __syncthreads();

#pragma unroll
        for (int kk = 0; kk < 32; kk += 16) {
            uint32_t fah[2][4], fal[2][4], fbh[8][2], fbl[8][2];
            const int ar = lane & 15, ac = kk + ((lane >> 4) & 1) * 8;
            const int br = lane & 7,  bc = kk + ((lane >> 3) & 1) * 8;
#pragma unroll
            for (int mf = 0; mf < 2; mf++) {
                ldmA4(fah[mf], &Ah[m0 + mf * 16 + ar][ac]);
                ldmA4(fal[mf], &Al[m0 + mf * 16 + ar][ac]);
            }
#pragma unroll
            for (int nf = 0; nf < 8; nf++) {
                ldmB2(fbh[nf], &Bh[n0 + nf * 8 + br][bc]);
                ldmB2(fbl[nf], &Bl[n0 + nf * 8 + br][bc]);
            }
#pragma unroll
            for (int nf = 0; nf < 8; nf++)
#pragma unroll
                for (int mf = 0; mf < 2; mf++) mma_bf16(acc[mf][nf], fah[mf], fbh[nf]);
#pragma unroll
            for (int nf = 0; nf < 8; nf++)
#pragma unroll
                for (int mf = 0; mf < 2; mf++) mma_bf16(acc[mf][nf], fah[mf], fbl[nf]);
#pragma unroll
            for (int nf = 0; nf < 8; nf++)
#pragma unroll
                for (int mf = 0; mf < 2; mf++) mma_bf16(acc[mf][nf], fal[mf], fbh[nf]);
        }
        __syncthreads();
    }

    // epilogue: +bias, re-split, scatter. q,k -> [b,h,s,d]; v -> [b,h,d,s].
    const int r = lane >> 2, cp = (lane & 3) * 2;
#pragma unroll
    for (int mf = 0; mf < 2; mf++) {
#pragma unroll
        for (int nf = 0; nf < 8; nf++) {
            const int col = n0 + nf * 8 + cp;
            const int oc = oc0 + col;
            const int h = oc >> 6, d = oc & 63;
            const float b0 = bias[oc], b1 = bias[oc + 1];
#pragma unroll
            for (int half = 0; half < 2; half++) {
                const int s = sl0 + m0 + mf * 16 + r + half * 8;
                bf16 h0, l0, h1, l1;
                split2(acc[mf][nf][half * 2 + 0] + b0, h0, l0);
                split2(acc[mf][nf][half * 2 + 1] + b1, h1, l1);
                if (seg < 2) {
                    bf16* Dh = (seg == 0) ? g_qh : g_kh;
                    bf16* Dl = (seg == 0) ? g_ql : g_kl;
                    const size_t idx = (((size_t)((b * NH + h) * SEQ + s)) << 6) + d;
                    *(__nv_bfloat162*)(Dh + idx) = __nv_bfloat162(h0, h1);
                    *(__nv_bfloat162*)(Dl + idx) = __nv_bfloat162(l0, l1);
                } else {
                    const size_t base = ((size_t)((b * NH + h) * 64 + d)) * SEQ + s;
                    g_vth[base] = h0; g_vtl[base] = l0;
                    g_vth[base + SEQ] = h1; g_vtl[base + SEQ] = l1;
                }
            }
        }
    }
}

// ---------------------------------------------------------------------------
// Scores: 128x128 tile per block (jt <= rt), K=64, bf16x3 on tensor cores.
// ---------------------------------------------------------------------------
__global__ void __launch_bounds__(256)
scores_kernel(float* __restrict__ attn)
{
    const int jt = blockIdx.x, rt = blockIdx.y, bhid = blockIdx.z;
    if (jt > rt) return;
    extern __shared__ bf16 sm[];
    bf16* Qh = sm;                // [128][72]
    bf16* Ql = Qh + 128 * 72;
    bf16* Kh = Ql + 128 * 72;
    bf16* Kl = Kh + 128 * 72;

    const int r0 = rt * 128, j0 = jt * 128;
    const int tid = threadIdx.x, lane = tid & 31, wid = tid >> 5;
    const int m0 = (wid >> 1) * 32, n0 = (wid & 1) * 64;

#pragma unroll
    for (int it = 0; it < 4; it++) {
        const int idx = tid + it * 256;
        const int row = idx >> 3, q8 = (idx & 7) * 8;
        const size_t qo = (((size_t)bhid * SEQ) + r0 + row) * 64 + q8;
        const size_t ko = (((size_t)bhid * SEQ) + j0 + row) * 64 + q8;
        *(uint4*)&Qh[row * 72 + q8] = *(const uint4*)(g_qh + qo);
        *(uint4*)&Ql[row * 72 + q8] = *(const uint4*)(g_ql + qo);
        *(uint4*)&Kh[row * 72 + q8] = *(const uint4*)(g_kh + ko);
        *(uint4*)&Kl[row * 72 + q8] = *(const uint4*)(g_kl + ko);
    }
    __syncthreads();

    float acc[2][8][4];
#pragma unroll
    for (int i = 0; i < 2; i++)
#pragma unroll
        for (int j = 0; j < 8; j++)
#pragma unroll
            for (int c = 0; c < 4; c++) acc[i][j][c] = 0.f;

#pragma unroll
    for (int kk = 0; kk < 64; kk += 16) {
        uint32_t fah[2][4], fal[2][4], fbh[8][2], fbl[8][2];
        const int ar = lane & 15, ac = kk + ((lane >> 4) & 1) * 8;
        const int br = lane & 7,  bc = kk + ((lane >> 3) & 1) * 8;
#pragma unroll
        for (int mf = 0; mf < 2; mf++) {
            ldmA4(fah[mf], &Qh[(m0 + mf * 16 + ar) * 72 + ac]);
            ldmA4(fal[mf], &Ql[(m0 + mf * 16 + ar) * 72 + ac]);
        }
#pragma unroll
        for (int nf = 0; nf < 8; nf++) {
            ldmB2(fbh[nf], &Kh[(n0 + nf * 8 + br) * 72 + bc]);
            ldmB2(fbl[nf], &Kl[(n0 + nf * 8 + br) * 72 + bc]);
        }
#pragma unroll
        for (int nf = 0; nf < 8; nf++)
#pragma unroll
            for (int mf = 0; mf < 2; mf++) mma_bf16(acc[mf][nf], fah[mf], fbh[nf]);
#pragma unroll
        for (int nf = 0; nf < 8; nf++)
#pragma unroll
            for (int mf = 0; mf < 2; mf++) mma_bf16(acc[mf][nf], fah[mf], fbl[nf]);
#pragma unroll
        for (int nf = 0; nf < 8; nf++)
#pragma unroll
            for (int mf = 0; mf < 2; mf++) mma_bf16(acc[mf][nf], fal[mf], fbh[nf]);
    }

    const int r = lane >> 2, cp = (lane & 3) * 2;
#pragma unroll
    for (int mf = 0; mf < 2; mf++)
#pragma unroll
        for (int nf = 0; nf < 8; nf++) {
            const int jcol = j0 + n0 + nf * 8 + cp;
#pragma unroll
            for (int half = 0; half < 2; half++) {
                const int rr = r0 + m0 + mf * 16 + r + half * 8;
                float2 o;
                o.x = acc[mf][nf][half * 2 + 0] * 0.125f;
                o.y = acc[mf][nf][half * 2 + 1] * 0.125f;
                *(float2*)(attn + (((size_t)bhid * SEQ) + rr) * SEQ + jcol) = o;
            }
        }
}

// ---------------------------------------------------------------------------
// Softmax: one block / row, float4-vectorized, exact zeros above diagonal.
// ---------------------------------------------------------------------------
__global__ void __launch_bounds__(256)
softmax_kernel(float* __restrict__ attn)
{
    const int row = blockIdx.x;
    const int bhid = row >> 11, sl = row & 2047;
    float* e = attn + (((size_t)bhid * SEQ) + sl) * SEQ;
    const int len = sl + 1;
    const int n4 = (len + 3) >> 2;
    const int tid = threadIdx.x;
    float4* e4 = (float4*)e;

    float buf[8];
    float m = -1e30f;
#pragma unroll
    for (int it = 0; it < 2; it++) {
        const int j4 = tid + it * 256;
        float4 v = make_float4(-1e30f, -1e30f, -1e30f, -1e30f);
        if (j4 < n4) v = e4[j4];
        const int jb = j4 << 2;
        if (jb + 0 >= len) v.x = -1e30f;
        if (jb + 1 >= len) v.y = -1e30f;
        if (jb + 2 >= len) v.z = -1e30f;
        if (jb + 3 >= len) v.w = -1e30f;
        buf[it * 4 + 0] = v.x; buf[it * 4 + 1] = v.y;
        buf[it * 4 + 2] = v.z; buf[it * 4 + 3] = v.w;
        m = fmaxf(m, fmaxf(fmaxf(v.x, v.y), fmaxf(v.z, v.w)));
    }
    __shared__ float red[8];
#pragma unroll
    for (int o = 16; o; o >>= 1) m = fmaxf(m, __shfl_xor_sync(~0u, m, o));
    if ((tid & 31) == 0) red[tid >> 5] = m;
    __syncthreads();
    const float M = fmaxf(fmaxf(fmaxf(red[0], red[1]), fmaxf(red[2], red[3])),
                          fmaxf(fmaxf(red[4], red[5]), fmaxf(red[6], red[7])));
    __syncthreads();

    float s = 0.f;
#pragma unroll
    for (int i = 0; i < 8; i++) { buf[i] = __expf(buf[i] - M); s += buf[i]; }
#pragma unroll
    for (int o = 16; o; o >>= 1) s += __shfl_xor_sync(~0u, s, o);
    if ((tid & 31) == 0) red[tid >> 5] = s;
    __syncthreads();
    const float inv = 1.f / (red[0] + red[1] + red[2] + red[3] +
                             red[4] + red[5] + red[6] + red[7]);

#pragma unroll
    for (int it = 0; it < 2; it++) {
        const int j4 = tid + it * 256;
        float4 o = make_float4(0.f, 0.f, 0.f, 0.f);
        if (j4 < n4) {
            o.x = buf[it * 4 + 0] * inv;
            o.y = buf[it * 4 + 1] * inv;
            o.z = buf[it * 4 + 2] * inv;
            o.w = buf[it * 4 + 3] * inv;
        }
        e4[j4] = o;
    }
}

// ---------------------------------------------------------------------------
// PV: block tile 128(r) x 64(d). P read fp32 once and split in staging;
// V pre-transposed [b,h,d,s] so B operand is n-major. P exact-zero above diag.
// ---------------------------------------------------------------------------
__global__ void __launch_bounds__(256)
pv_kernel(const float* __restrict__ attn, float* __restrict__ out)
{
    const int rt = blockIdx.x;            // 16
    const int bhid = blockIdx.y;          // 32
    const int b = bhid >> 3, h = bhid & 7;
    const int r0 = rt * 128;
    extern __shared__ bf16 sm[];
    bf16* Ph = sm;                 // [128][72]
    bf16* Pl = Ph + 128 * 72;
    bf16* Vh = Pl + 128 * 72;      // [64][72]
    bf16* Vl = Vh + 64 * 72;

    const int tid = threadIdx.x, lane = tid & 31, wid = tid >> 5;
    const int m0 = (wid >> 1) * 32, n0 = (wid & 1) * 32;

    float acc[2][4][4];
#pragma unroll
    for (int i = 0; i < 2; i++)
#pragma unroll
        for (int j = 0; j < 4; j++)
#pragma unroll
            for (int c = 0; c < 4; c++) acc[i][j][c] = 0.f;

    for (int j0 = 0; j0 < r0 + 128; j0 += 64) {
#pragma unroll
        for (int it = 0; it < 8; it++) {
            const int idx = tid + it * 256;
            const int row = idx >> 4, j4 = (idx & 15) * 4;
            const float4 v = *(const float4*)(attn + (((size_t)bhid * SEQ) + r0 + row) * SEQ + j0 + j4);
            bf16 h0,l0,h1,l1,h2,l2,h3,l3;
            split2(v.x, h0, l0); split2(v.y, h1, l1);
            split2(v.z, h2, l2); split2(v.w, h3, l3);
            *(__nv_bfloat162*)&Ph[row * 72 + j4]     = __nv_bfloat162(h0, h1);
            *(__nv_bfloat162*)&Ph[row * 72 + j4 + 2] = __nv_bfloat162(h2, h3);
            *(__nv_bfloat162*)&Pl[row * 72 + j4]     = __nv_bfloat162(l0, l1);
            *(__nv_bfloat162*)&Pl[row * 72 + j4 + 2] = __nv_bfloat162(l2, l3);
        }
#pragma unroll
        for (int it = 0; it < 2; it++) {
            const int idx = tid + it * 256;
            const int d = idx >> 3, q8 = (idx & 7) * 8;
            const size_t off = (((size_t)bhid * 64) + d) * SEQ + j0 + q8;
            *(uint4*)&Vh[d * 72 + q8] = *(const uint4*)(g_vth + off);
            *(uint4*)&Vl[d * 72 + q8] = *(const uint4*)(g_vtl + off);
        }
        __syncthreads();

#pragma unroll
        for (int kk = 0; kk < 64; kk += 16) {
            uint32_t fah[2][4], fal[2][4], fbh[4][2], fbl[4][2];
            const int ar = lane & 15, ac = kk + ((lane >> 4) & 1) * 8;
            const int br = lane & 7,  bc = kk + ((lane >> 3) & 1) * 8;
#pragma unroll
            for (int mf = 0; mf < 2; mf++) {
                ldmA4(fah[mf], &Ph[(m0 + mf * 16 + ar) * 72 + ac]);
                ldmA4(fal[mf], &Pl[(m0 + mf * 16 + ar) * 72 + ac]);
            }
#pragma unroll
            for (int nf = 0; nf < 4; nf++) {
                ldmB2(fbh[nf], &Vh[(n0 + nf * 8 + br) * 72 + bc]);
                ldmB2(fbl[nf], &Vl[(n0 + nf * 8 + br) * 72 + bc]);
            }
#pragma unroll
            for (int nf = 0; nf < 4; nf++)
#pragma unroll
                for (int mf = 0; mf < 2; mf++) mma_bf16(acc[mf][nf], fah[mf], fbh[nf]);
#pragma unroll
            for (int nf = 0; nf < 4; nf++)
#pragma unroll
                for (int mf = 0; mf < 2; mf++) mma_bf16(acc[mf][nf], fah[mf], fbl[nf]);
#pragma unroll
            for (int nf = 0; nf < 4; nf++)
#pragma unroll
                for (int mf = 0; mf < 2; mf++) mma_bf16(acc[mf][nf], fal[mf], fbh[nf]);
        }
        __syncthreads();
    }

    const int r = lane >> 2, cp = (lane & 3) * 2;
#pragma unroll
    for (int mf = 0; mf < 2; mf++)
#pragma unroll
        for (int nf = 0; nf < 4; nf++) {
            const int d = n0 + nf * 8 + cp;
#pragma unroll
            for (int half = 0; half < 2; half++) {
                const int s = r0 + m0 + mf * 16 + r + half * 8;
                float2 o;
                o.x = acc[mf][nf][half * 2 + 0];
                o.y = acc[mf][nf][half * 2 + 1];
                *(float2*)(out + ((((size_t)(b * SEQ + s)) * NH + h) << 6) + d) = o;
            }
        }
}

extern "C" void kernel_launch(void* const* d_in, const int* in_sizes, int n_in,
                              void* d_out, int out_size)
{
    const float* x  = (const float*)d_in[0];
    // d_in[1] = mask (static causal) — unused
    const float* wq = (const float*)d_in[2];
    const float* bq = (const float*)d_in[3];
    const float* wk = (const float*)d_in[4];
    const float* bk = (const float*)d_in[5];
    const float* wv = (const float*)d_in[6];
    const float* bv = (const float*)d_in[7];

    float* out  = (float*)d_out;
    float* attn = out + (size_t)Bsz * SEQ * NH * 64;

    split_x_kernel<<<(Bsz*SEQ*CH + 255) / 256, 256>>>(x);
    repack_kernel<<<(CH * 1536 + 255) / 256, 256>>>(wq, wk, wv);
    qkv_gemm<<<dim3(64, 12), 256>>>(bq, bk, bv);

    const int sc_smem = 4 * 128 * 72 * (int)sizeof(bf16);   // 73728
    cudaFuncSetAttribute(scores_kernel, cudaFuncAttributeMaxDynamicSharedMemorySize, sc_smem);
    scores_kernel<<<dim3(16, 16, 32), 256, sc_smem>>>(attn);

    softmax_kernel<<<Bsz * NH * SEQ, 256>>>(attn);

    const int pv_smem = (2 * 128 * 72 + 2 * 64 * 72) * (int)sizeof(bf16);  // 55296
    cudaFuncSetAttribute(pv_kernel, cudaFuncAttributeMaxDynamicSharedMemorySize, pv_smem);
    pv_kernel<<<dim3(16, 32), 256, pv_smem>>>(attn, out);
}